// round 2
// baseline (speedup 1.0000x reference)
#include <cuda_runtime.h>
#include <math.h>

// ---------------- problem constants ----------------
#define BB 2
#define LL 4096
#define DM 1024
#define DIN 2048
#define NH 32
#define HD 64
#define DS 128
#define CHUNKSZ 256
#define NCHK 16
#define CONVDIM 2304        // DIN + 2*DS
#define DPROJ 4384          // 2*DIN + 2*DS + NH
#define NTOK (BB*LL)        // 8192
#define EPSV 1e-5f

// ---------------- scratch (device globals; no allocs allowed) ----------------
__device__ float g_xnorm[(size_t)NTOK*DM];              // 33.5 MB
__device__ float g_zxbcdt[(size_t)NTOK*DPROJ];          // 143.7 MB
__device__ float g_xBCc[(size_t)NTOK*CONVDIM];          // 75.5 MB
__device__ float g_dtv[(size_t)NTOK*NH];                // 1 MB
__device__ float g_Acum[(size_t)BB*NCHK*NH*CHUNKSZ];    // 1 MB
__device__ float g_G[(size_t)BB*NCHK*CHUNKSZ*CHUNKSZ];  // 8.4 MB
__device__ float g_states[(size_t)BB*NCHK*NH*HD*DS];    // 33.6 MB
__device__ float g_prevS[(size_t)BB*NCHK*NH*HD*DS];     // 33.6 MB
__device__ float g_ydiag[(size_t)NTOK*DIN];             // 67 MB (also final y, updated in place)
__device__ float g_yg[(size_t)NTOK*DIN];                // 67 MB

__device__ __forceinline__ float siluf(float x){ return x / (1.f + __expf(-x)); }

// ---------------- K1: RMSNorm over D_MODEL=1024 ----------------
__global__ __launch_bounds__(256) void rmsnorm_kernel(const float* __restrict__ x,
                                                      const float* __restrict__ w,
                                                      float* __restrict__ out){
    int row = blockIdx.x;
    int t = threadIdx.x;
    float4 v = ((const float4*)(x + (size_t)row*DM))[t];
    float ss = v.x*v.x + v.y*v.y + v.z*v.z + v.w*v.w;
    __shared__ float red[8];
    for (int o=16;o>0;o>>=1) ss += __shfl_down_sync(0xffffffffu, ss, o);
    if ((t&31)==0) red[t>>5] = ss;
    __syncthreads();
    if (t < 32){
        float s2 = (t<8)? red[t] : 0.f;
        for (int o=4;o>0;o>>=1) s2 += __shfl_down_sync(0xffffffffu, s2, o);
        if (t==0) red[0] = s2;
    }
    __syncthreads();
    float scale = rsqrtf(red[0]/(float)DM + EPSV);
    float4 wv = ((const float4*)w)[t];
    float4 o4 = make_float4(v.x*scale*wv.x, v.y*scale*wv.y, v.z*scale*wv.z, v.w*scale*wv.w);
    ((float4*)(out + (size_t)row*DM))[t] = o4;
}

// ---------------- K2/K12: SGEMM, C = A(MxK) @ B(KxN) [+ Cadd] ----------------
__global__ __launch_bounds__(256) void sgemm_kernel(int M, int N, int K,
                                                    const float* __restrict__ A,
                                                    const float* __restrict__ B,
                                                    const float* __restrict__ Cadd,
                                                    float* __restrict__ C){
    const int BM=128, BN=128, BK=8, TM=8, TN=8;
    __shared__ float As[BK][BM];
    __shared__ float Bs[BK][BN];
    int tid = threadIdx.x;
    int brow = blockIdx.y, bcol = blockIdx.x;
    int tcol = tid & 15, trow = tid >> 4;
    float acc[TM][TN];
    #pragma unroll
    for (int i=0;i<TM;i++)
        #pragma unroll
        for (int j=0;j<TN;j++) acc[i][j] = 0.f;
    float regM[TM], regN[TN];

    int aInnerRow = tid >> 1;
    int aInnerCol = (tid & 1) * 4;
    int bInnerRow = tid >> 5;
    int bInnerCol = (tid & 31) * 4;

    const float* Ab = A + (size_t)(brow*BM)*K;
    int colBase = bcol*BN;
    bool fullN = (colBase + BN <= N);

    for (int k0=0; k0<K; k0+=BK){
        float4 av = *(const float4*)(Ab + (size_t)aInnerRow*K + k0 + aInnerCol);
        As[aInnerCol+0][aInnerRow] = av.x;
        As[aInnerCol+1][aInnerRow] = av.y;
        As[aInnerCol+2][aInnerRow] = av.z;
        As[aInnerCol+3][aInnerRow] = av.w;
        if (fullN){
            float4 bv = *(const float4*)(B + (size_t)(k0+bInnerRow)*N + colBase + bInnerCol);
            *(float4*)&Bs[bInnerRow][bInnerCol] = bv;
        } else {
            #pragma unroll
            for (int j=0;j<4;j++){
                int col = colBase + bInnerCol + j;
                Bs[bInnerRow][bInnerCol+j] = (col < N) ? B[(size_t)(k0+bInnerRow)*N + col] : 0.f;
            }
        }
        __syncthreads();
        #pragma unroll
        for (int k=0;k<BK;k++){
            #pragma unroll
            for (int i=0;i<TM;i++) regM[i] = As[k][trow*TM+i];
            #pragma unroll
            for (int j=0;j<TN;j++) regN[j] = Bs[k][tcol*TN+j];
            #pragma unroll
            for (int i=0;i<TM;i++)
                #pragma unroll
                for (int j=0;j<TN;j++) acc[i][j] += regM[i]*regN[j];
        }
        __syncthreads();
    }
    #pragma unroll
    for (int i=0;i<TM;i++){
        int row = brow*BM + trow*TM + i;
        #pragma unroll
        for (int j=0;j<TN;j+=4){
            int col = colBase + tcol*TN + j;
            if (col + 3 < N){
                float4 v = make_float4(acc[i][j],acc[i][j+1],acc[i][j+2],acc[i][j+3]);
                if (Cadd){
                    float4 r = *(const float4*)(Cadd + (size_t)row*N + col);
                    v.x += r.x; v.y += r.y; v.z += r.z; v.w += r.w;
                }
                *(float4*)(C + (size_t)row*N + col) = v;
            } else {
                for (int jj=0;jj<4;jj++){
                    int c2 = col + jj;
                    if (c2 < N){
                        float v = acc[i][j+jj];
                        if (Cadd) v += Cadd[(size_t)row*N + c2];
                        C[(size_t)row*N + c2] = v;
                    }
                }
            }
        }
    }
}

// ---------------- K3: causal depthwise conv1d (k=4) + bias + SiLU ----------------
__global__ void conv_kernel(const float* __restrict__ zx, const float* __restrict__ cw,
                            const float* __restrict__ cb, float* __restrict__ out){
    int idx = blockIdx.x*blockDim.x + threadIdx.x;
    if (idx >= NTOK*CONVDIM) return;
    int c = idx % CONVDIM;
    int row = idx / CONVDIM;
    int l = row & (LL-1);
    float acc = cb[c];
    #pragma unroll
    for (int k=0;k<4;k++){
        int ls = l - 3 + k;
        if (ls >= 0) acc += zx[(size_t)(row-3+k)*DPROJ + DIN + c] * cw[c*4+k];
    }
    out[(size_t)row*CONVDIM + c] = siluf(acc);
}

// ---------------- K4: dt = softplus(dt_raw + dt_bias) ----------------
__global__ void dt_kernel(const float* __restrict__ zx, const float* __restrict__ dt_bias,
                          float* __restrict__ dtv){
    int idx = blockIdx.x*blockDim.x + threadIdx.x;
    if (idx >= NTOK*NH) return;
    int h = idx & (NH-1);
    int row = idx / NH;
    float x = zx[(size_t)row*DPROJ + (DIN + CONVDIM) + h] + dt_bias[h];
    dtv[idx] = (x > 20.f) ? x : log1pf(expf(x));
}

// ---------------- K5: per-(b,c,h) inclusive cumsum of dt*A over chunk ----------------
__global__ __launch_bounds__(256) void cumsum_kernel(const float* __restrict__ dtv,
                                                     const float* __restrict__ A_log,
                                                     float* __restrict__ Acum){
    int bid = blockIdx.x;                    // (b*NCHK + c)*NH + h
    int h = bid % NH; int c = (bid/NH) % NCHK; int b = bid/(NH*NCHK);
    int t = threadIdx.x;
    int row = b*LL + c*CHUNKSZ + t;
    float negA = -expf(A_log[h]);
    float v = dtv[(size_t)row*NH + h] * negA;
    __shared__ float sh[256];
    sh[t] = v; __syncthreads();
    for (int off=1; off<256; off<<=1){
        float add = (t >= off) ? sh[t-off] : 0.f;
        __syncthreads();
        sh[t] += add;
        __syncthreads();
    }
    Acum[(size_t)bid*CHUNKSZ + t] = sh[t];
}

// ---------------- K6: G[l,s] = sum_n C[l,n]*B[s,n], per (b,c) ----------------
__global__ __launch_bounds__(256) void gmat_kernel(const float* __restrict__ xbc,
                                                   float* __restrict__ G){
    int bc = blockIdx.z;
    int b = bc / NCHK, c = bc % NCHK;
    int lt = blockIdx.x*16, st = blockIdx.y*16;
    __shared__ float Cs[16][129];
    __shared__ float Bs[16][129];
    int t = threadIdx.y*16 + threadIdx.x;
    int rowbase = b*LL + c*CHUNKSZ;
    #pragma unroll
    for (int i=0;i<8;i++){
        int f = i*256 + t; int r = f >> 7, col = f & 127;
        Cs[r][col] = xbc[(size_t)(rowbase+lt+r)*CONVDIM + 2176 + col];
        Bs[r][col] = xbc[(size_t)(rowbase+st+r)*CONVDIM + 2048 + col];
    }
    __syncthreads();
    float acc = 0.f;
    #pragma unroll 8
    for (int n=0;n<128;n++) acc += Cs[threadIdx.y][n]*Bs[threadIdx.x][n];
    G[((size_t)bc*CHUNKSZ + lt + threadIdx.y)*CHUNKSZ + st + threadIdx.x] = acc;
}

// ---------------- K7: Y_diag per (b,c,h); thread = l, acc over p ----------------
__global__ __launch_bounds__(256) void ydiag_kernel(const float* __restrict__ xbc,
                                                    const float* __restrict__ dtv,
                                                    const float* __restrict__ Acum,
                                                    const float* __restrict__ G,
                                                    float* __restrict__ ydiag){
    int bid = blockIdx.x;
    int h = bid % NH; int c = (bid/NH) % NCHK; int b = bid/(NH*NCHK);
    int t = threadIdx.x;                     // l within chunk
    int bc = b*NCHK + c;
    int rowbase = b*LL + c*CHUNKSZ;
    const float* Gb = G + (size_t)bc*CHUNKSZ*CHUNKSZ;

    __shared__ float Gs[256*33];
    __shared__ float xs[32*64];
    __shared__ float Acs[32];
    __shared__ float dts[32];

    float a_l = Acum[(size_t)bid*CHUNKSZ + t];
    float acc[64];
    #pragma unroll
    for (int p=0;p<64;p++) acc[p] = 0.f;

    for (int s0=0; s0<CHUNKSZ; s0+=32){
        #pragma unroll 4
        for (int i=0;i<32;i++){
            int f = i*256 + t; int r = f >> 5, col = f & 31;
            Gs[r*33+col] = Gb[(size_t)r*CHUNKSZ + s0 + col];
        }
        #pragma unroll
        for (int i=0;i<8;i++){
            int f = i*256 + t; int s = f >> 6, p = f & 63;
            xs[s*64+p] = xbc[(size_t)(rowbase+s0+s)*CONVDIM + h*HD + p];
        }
        if (t < 32){
            Acs[t] = Acum[(size_t)bid*CHUNKSZ + s0 + t];
            dts[t] = dtv[(size_t)(rowbase+s0+t)*NH + h];
        }
        __syncthreads();
        if (s0 <= t){
            int smax = t - s0 + 1; if (smax > 32) smax = 32;
            for (int s=0;s<smax;s++){
                float coef = Gs[t*33+s] * __expf(a_l - Acs[s]) * dts[s];
                const float* xp = &xs[s*64];
                #pragma unroll
                for (int p=0;p<64;p++) acc[p] += coef * xp[p];
            }
        }
        __syncthreads();
    }
    float* yo = ydiag + (size_t)(rowbase+t)*DIN + h*HD;
    #pragma unroll
    for (int p=0;p<64;p+=4)
        *(float4*)(yo+p) = make_float4(acc[p],acc[p+1],acc[p+2],acc[p+3]);
}

// ---------------- K8: chunk states per (b,c,h): states[p,n] ----------------
__global__ __launch_bounds__(256) void states_kernel(const float* __restrict__ xbc,
                                                     const float* __restrict__ dtv,
                                                     const float* __restrict__ Acum,
                                                     float* __restrict__ states){
    int bid = blockIdx.x;
    int h = bid % NH; int c = (bid/NH) % NCHK; int b = bid/(NH*NCHK);
    int t = threadIdx.x;
    int p = t & 63, ng = t >> 6;
    int rowbase = b*LL + c*CHUNKSZ;

    __shared__ float xs[32*64];
    __shared__ float Bsh[32*128];
    __shared__ float cl[32];

    float Atot = Acum[(size_t)bid*CHUNKSZ + 255];
    float acc[32];
    #pragma unroll
    for (int j=0;j<32;j++) acc[j] = 0.f;

    for (int l0=0; l0<CHUNKSZ; l0+=32){
        #pragma unroll
        for (int i=0;i<8;i++){
            int f = i*256 + t; int s = f >> 6, pp = f & 63;
            xs[s*64+pp] = xbc[(size_t)(rowbase+l0+s)*CONVDIM + h*HD + pp];
        }
        #pragma unroll
        for (int i=0;i<16;i++){
            int f = i*256 + t; int r = f >> 7, n = f & 127;
            Bsh[r*128+n] = xbc[(size_t)(rowbase+l0+r)*CONVDIM + 2048 + n];
        }
        if (t < 32){
            int l = l0 + t;
            cl[t] = dtv[(size_t)(rowbase+l)*NH + h] * __expf(Atot - Acum[(size_t)bid*CHUNKSZ + l]);
        }
        __syncthreads();
        for (int l=0;l<32;l++){
            float v = xs[l*64+p] * cl[l];
            const float* bp = &Bsh[l*128 + ng*32];
            #pragma unroll
            for (int j=0;j<32;j++) acc[j] += v * bp[j];
        }
        __syncthreads();
    }
    float* so = states + ((size_t)bid*HD + p)*DS + ng*32;
    #pragma unroll
    for (int j=0;j<32;j+=4)
        *(float4*)(so+j) = make_float4(acc[j],acc[j+1],acc[j+2],acc[j+3]);
}

// ---------------- K9: inter-chunk scan (recurrence over 16 chunks) ----------------
__global__ void scan_kernel(const float* __restrict__ states, const float* __restrict__ Acum,
                            float* __restrict__ prevS){
    int idx = blockIdx.x*blockDim.x + threadIdx.x;   // over b,h,p,n = 2^19
    if (idx >= BB*NH*HD*DS) return;
    int n = idx & 127;
    int p = (idx >> 7) & 63;
    int h = (idx >> 13) & 31;
    int b = idx >> 18;
    float S = 0.f;
    for (int c=0;c<NCHK;c++){
        int bid = (b*NCHK + c)*NH + h;
        size_t off = ((size_t)bid*HD + p)*DS + n;
        prevS[off] = S;
        float T = Acum[(size_t)bid*CHUNKSZ + 255];
        S = expf(T)*S + states[off];
    }
}

// ---------------- K10: Y_off + combine (in place into ydiag) ----------------
__global__ __launch_bounds__(256) void yoff_kernel(const float* __restrict__ xbc,
                                                   const float* __restrict__ Acum,
                                                   const float* __restrict__ prevS,
                                                   const float* __restrict__ Dskip,
                                                   float* __restrict__ y){
    int bid = blockIdx.x;
    int h = bid % NH; int c = (bid/NH) % NCHK; int b = bid/(NH*NCHK);
    int t = threadIdx.x;                     // l
    int rowbase = b*LL + c*CHUNKSZ;

    __shared__ float Ss[64*64];
    __shared__ float Cs[256*17];

    float acc[64];
    #pragma unroll
    for (int p=0;p<64;p++) acc[p] = 0.f;
    const float* Sb = prevS + (size_t)bid*HD*DS;

    for (int half=0; half<2; half++){
        int n0h = half*64;
        __syncthreads();   // prior compute done before overwriting Ss
        #pragma unroll
        for (int i=0;i<16;i++){
            int f = i*256 + t; int pp = f >> 6, j = f & 63;
            Ss[pp*64+j] = Sb[(size_t)pp*DS + n0h + j];
        }
        for (int sub=0; sub<4; sub++){
            int n0 = n0h + sub*16;
            __syncthreads();   // prior compute done / Ss visible
            #pragma unroll
            for (int i=0;i<16;i++){
                int f = i*256 + t; int r = f >> 4, cc = f & 15;
                Cs[r*17+cc] = xbc[(size_t)(rowbase+r)*CONVDIM + 2176 + n0 + cc];
            }
            __syncthreads();
            for (int j=0;j<16;j++){
                float cv = Cs[t*17+j];
                int lc = sub*16 + j;
                #pragma unroll
                for (int p=0;p<64;p++) acc[p] += cv * Ss[p*64+lc];
            }
        }
    }
    float e = __expf(Acum[(size_t)bid*CHUNKSZ + t]);
    float dsk = Dskip[h];
    const float* xrow = xbc + (size_t)(rowbase+t)*CONVDIM + h*HD;
    float* yo = y + (size_t)(rowbase+t)*DIN + h*HD;
    #pragma unroll
    for (int p=0;p<64;p+=4){
        float4 xd = *(const float4*)(xrow+p);
        float4 yd = *(const float4*)(yo+p);
        float4 o;
        o.x = yd.x + e*acc[p+0] + xd.x*dsk;
        o.y = yd.y + e*acc[p+1] + xd.y*dsk;
        o.z = yd.z + e*acc[p+2] + xd.z*dsk;
        o.w = yd.w + e*acc[p+3] + xd.w*dsk;
        *(float4*)(yo+p) = o;
    }
}

// ---------------- K11: gated RMSNorm over D_INNER=2048 ----------------
__global__ __launch_bounds__(256) void gatenorm_kernel(const float* __restrict__ y,
                                                       const float* __restrict__ zx,
                                                       const float* __restrict__ gw,
                                                       float* __restrict__ out){
    int row = blockIdx.x, t = threadIdx.x;
    const float* yr = y + (size_t)row*DIN;
    const float* zr = zx + (size_t)row*DPROJ;   // z = first DIN cols
    float vals[8]; float ss = 0.f;
    #pragma unroll
    for (int i=0;i<2;i++){
        int cbase = (i*256 + t)*4;
        float4 yv = *(const float4*)(yr + cbase);
        float4 zv = *(const float4*)(zr + cbase);
        float a;
        a = yv.x * siluf(zv.x); vals[i*4+0] = a; ss += a*a;
        a = yv.y * siluf(zv.y); vals[i*4+1] = a; ss += a*a;
        a = yv.z * siluf(zv.z); vals[i*4+2] = a; ss += a*a;
        a = yv.w * siluf(zv.w); vals[i*4+3] = a; ss += a*a;
    }
    __shared__ float red[8];
    for (int o=16;o>0;o>>=1) ss += __shfl_down_sync(0xffffffffu, ss, o);
    if ((t&31)==0) red[t>>5] = ss;
    __syncthreads();
    if (t < 32){
        float s2 = (t<8)? red[t] : 0.f;
        for (int o=4;o>0;o>>=1) s2 += __shfl_down_sync(0xffffffffu, s2, o);
        if (t==0) red[0] = s2;
    }
    __syncthreads();
    float scale = rsqrtf(red[0]/(float)DIN + EPSV);
    #pragma unroll
    for (int i=0;i<2;i++){
        int cbase = (i*256 + t)*4;
        float4 wv = *(const float4*)(gw + cbase);
        float4 o4 = make_float4(vals[i*4+0]*scale*wv.x, vals[i*4+1]*scale*wv.y,
                                vals[i*4+2]*scale*wv.z, vals[i*4+3]*scale*wv.w);
        *(float4*)(out + (size_t)row*DIN + cbase) = o4;
    }
}

// ---------------- launch ----------------
extern "C" void kernel_launch(void* const* d_in, const int* in_sizes, int n_in,
                              void* d_out, int out_size){
    const float* hidden  = (const float*)d_in[0];
    const float* norm_w  = (const float*)d_in[1];
    const float* in_proj = (const float*)d_in[2];
    const float* conv_w  = (const float*)d_in[3];
    const float* conv_b  = (const float*)d_in[4];
    const float* dt_bias = (const float*)d_in[5];
    const float* A_log   = (const float*)d_in[6];
    const float* Dsk     = (const float*)d_in[7];
    const float* gnw     = (const float*)d_in[8];
    const float* out_w   = (const float*)d_in[9];
    float* out = (float*)d_out;

    float *p_xnorm, *p_zx, *p_xbc, *p_dtv, *p_acum, *p_g, *p_states, *p_prevS, *p_ydiag, *p_yg;
    cudaGetSymbolAddress((void**)&p_xnorm, g_xnorm);
    cudaGetSymbolAddress((void**)&p_zx,    g_zxbcdt);
    cudaGetSymbolAddress((void**)&p_xbc,   g_xBCc);
    cudaGetSymbolAddress((void**)&p_dtv,   g_dtv);
    cudaGetSymbolAddress((void**)&p_acum,  g_Acum);
    cudaGetSymbolAddress((void**)&p_g,     g_G);
    cudaGetSymbolAddress((void**)&p_states,g_states);
    cudaGetSymbolAddress((void**)&p_prevS, g_prevS);
    cudaGetSymbolAddress((void**)&p_ydiag, g_ydiag);
    cudaGetSymbolAddress((void**)&p_yg,    g_yg);

    // 1. RMSNorm
    rmsnorm_kernel<<<NTOK, 256>>>(hidden, norm_w, p_xnorm);
    // 2. in_proj GEMM: [8192,1024] @ [1024,4384]
    sgemm_kernel<<<dim3((DPROJ+127)/128, NTOK/128), 256>>>(NTOK, DPROJ, DM, p_xnorm, in_proj, nullptr, p_zx);
    // 3. conv1d + bias + silu
    conv_kernel<<<(NTOK*CONVDIM + 255)/256, 256>>>(p_zx, conv_w, conv_b, p_xbc);
    // 4. dt softplus
    dt_kernel<<<(NTOK*NH + 255)/256, 256>>>(p_zx, dt_bias, p_dtv);
    // 5. per-chunk cumsum of dt*A
    cumsum_kernel<<<BB*NCHK*NH, 256>>>(p_dtv, A_log, p_acum);
    // 6. G = C @ B^T per (b,c)
    gmat_kernel<<<dim3(16,16,BB*NCHK), dim3(16,16)>>>(p_xbc, p_g);
    // 7. Y_diag
    ydiag_kernel<<<BB*NCHK*NH, 256>>>(p_xbc, p_dtv, p_acum, p_g, p_ydiag);
    // 8. chunk states
    states_kernel<<<BB*NCHK*NH, 256>>>(p_xbc, p_dtv, p_acum, p_states);
    // 9. inter-chunk scan
    scan_kernel<<<(BB*NH*HD*DS + 255)/256, 256>>>(p_states, p_acum, p_prevS);
    // 10. Y_off + combine + D skip (in place into ydiag)
    yoff_kernel<<<BB*NCHK*NH, 256>>>(p_xbc, p_acum, p_prevS, Dsk, p_ydiag);
    // 11. gated RMSNorm
    gatenorm_kernel<<<NTOK, 256>>>(p_ydiag, p_zx, gnw, p_yg);
    // 12. out_proj GEMM + residual: [8192,2048] @ [2048,1024] + hidden
    sgemm_kernel<<<dim3(DM/128, NTOK/128), 256>>>(NTOK, DM, DIN, p_yg, out_w, hidden, out);
}

// round 3
// speedup vs baseline: 1.9006x; 1.9006x over previous
#include <cuda_runtime.h>
#include <math.h>
#include <stdint.h>

// ---------------- problem constants ----------------
#define BB 2
#define LL 4096
#define DM 1024
#define DIN 2048
#define NH 32
#define HD 64
#define DS 128
#define CHUNKSZ 256
#define NCHK 16
#define CONVDIM 2304        // DIN + 2*DS
#define DPROJ 4384          // 2*DIN + 2*DS + NH
#define NTOK (BB*LL)        // 8192
#define EPSV 1e-5f

// ---------------- scratch (device globals; no allocs allowed) ----------------
__device__ float g_xnorm[(size_t)NTOK*DM];
__device__ float g_zxbcdt[(size_t)NTOK*DPROJ];
__device__ float g_xBCc[(size_t)NTOK*CONVDIM];
__device__ float g_dtv[(size_t)NTOK*NH];
__device__ float g_Acum[(size_t)BB*NCHK*NH*CHUNKSZ];
__device__ float g_G[(size_t)BB*NCHK*CHUNKSZ*CHUNKSZ];
__device__ float g_states[(size_t)BB*NCHK*NH*HD*DS];
__device__ float g_prevS[(size_t)BB*NCHK*NH*HD*DS];
__device__ float g_ydiag[(size_t)NTOK*DIN];             // also final y (in place)
__device__ float g_yg[(size_t)NTOK*DIN];

__device__ __forceinline__ float siluf(float x){ return x / (1.f + __expf(-x)); }

__device__ __forceinline__ uint32_t f2tf32(float x){
    uint32_t r;
    asm("cvt.rna.tf32.f32 %0, %1;" : "=r"(r) : "f"(x));
    return r;
}

#define MMA_TF32(c, a, b) \
    asm volatile("mma.sync.aligned.m16n8k8.row.col.f32.tf32.tf32.f32 " \
        "{%0,%1,%2,%3}, {%4,%5,%6,%7}, {%8,%9}, {%0,%1,%2,%3};" \
        : "+f"((c)[0]),"+f"((c)[1]),"+f"((c)[2]),"+f"((c)[3]) \
        : "r"((a)[0]),"r"((a)[1]),"r"((a)[2]),"r"((a)[3]), "r"((b)[0]),"r"((b)[1]))

// ---------------- K1: RMSNorm over D_MODEL=1024 ----------------
__global__ __launch_bounds__(256) void rmsnorm_kernel(const float* __restrict__ x,
                                                      const float* __restrict__ w,
                                                      float* __restrict__ out){
    int row = blockIdx.x;
    int t = threadIdx.x;
    float4 v = ((const float4*)(x + (size_t)row*DM))[t];
    float ss = v.x*v.x + v.y*v.y + v.z*v.z + v.w*v.w;
    __shared__ float red[8];
    for (int o=16;o>0;o>>=1) ss += __shfl_down_sync(0xffffffffu, ss, o);
    if ((t&31)==0) red[t>>5] = ss;
    __syncthreads();
    if (t < 32){
        float s2 = (t<8)? red[t] : 0.f;
        for (int o=4;o>0;o>>=1) s2 += __shfl_down_sync(0xffffffffu, s2, o);
        if (t==0) red[0] = s2;
    }
    __syncthreads();
    float scale = rsqrtf(red[0]/(float)DM + EPSV);
    float4 wv = ((const float4*)w)[t];
    float4 o4 = make_float4(v.x*scale*wv.x, v.y*scale*wv.y, v.z*scale*wv.z, v.w*scale*wv.w);
    ((float4*)(out + (size_t)row*DM))[t] = o4;
}

// ---------------- TF32 tensor-core GEMM: C = A(MxK) @ B(KxN) [+ Cadd] ----------------
// 128x128 block tile, BK=8, 8 warps (2x4), 64x32 warp tile, double-buffered smem.
#define SA 136
__global__ __launch_bounds__(256) void tf32gemm_kernel(int M, int N, int K,
                                                       const float* __restrict__ A,
                                                       const float* __restrict__ B,
                                                       const float* __restrict__ Cadd,
                                                       float* __restrict__ C){
    __shared__ uint32_t As[2][8*SA];
    __shared__ uint32_t Bs[2][8*SA];

    int tid = threadIdx.x;
    int lane = tid & 31;
    int warp = tid >> 5;
    int warpM = warp & 1;           // 2 warps over M
    int warpN = warp >> 1;          // 4 warps over N
    int gid = lane >> 2;            // 0..7
    int tg  = lane & 3;             // 0..3

    int colBase = blockIdx.x*128;
    const float* Ab = A + (size_t)(blockIdx.y*128)*K;
    bool fullN = (colBase + 128 <= N);

    // global-load mapping
    int aRow = tid >> 1, aK = (tid & 1)*4;              // A: 128 rows x 8 k
    int bK = tid >> 5, bN = (tid & 31)*4;               // B: 8 k x 128 n

    float acc[4][4][4];
    #pragma unroll
    for (int mt=0;mt<4;mt++)
        #pragma unroll
        for (int nt=0;nt<4;nt++)
            #pragma unroll
            for (int i=0;i<4;i++) acc[mt][nt][i] = 0.f;

    float4 aReg, bReg;

    // prefetch tile 0
    aReg = *(const float4*)(Ab + (size_t)aRow*K + aK);
    if (fullN){
        bReg = *(const float4*)(B + (size_t)bK*N + colBase + bN);
    } else {
        float tmp[4];
        #pragma unroll
        for (int j=0;j<4;j++){
            int col = colBase + bN + j;
            tmp[j] = (col < N) ? B[(size_t)bK*N + col] : 0.f;
        }
        bReg = make_float4(tmp[0],tmp[1],tmp[2],tmp[3]);
    }
    {
        As[0][(aK+0)*SA + aRow] = f2tf32(aReg.x);
        As[0][(aK+1)*SA + aRow] = f2tf32(aReg.y);
        As[0][(aK+2)*SA + aRow] = f2tf32(aReg.z);
        As[0][(aK+3)*SA + aRow] = f2tf32(aReg.w);
        uint4 bv = make_uint4(f2tf32(bReg.x),f2tf32(bReg.y),f2tf32(bReg.z),f2tf32(bReg.w));
        *(uint4*)&Bs[0][bK*SA + bN] = bv;
    }
    __syncthreads();

    int KT = K >> 3;
    for (int kt=0; kt<KT; kt++){
        int buf = kt & 1;
        // prefetch next tile into regs
        if (kt+1 < KT){
            int k0 = (kt+1)*8;
            aReg = *(const float4*)(Ab + (size_t)aRow*K + k0 + aK);
            if (fullN){
                bReg = *(const float4*)(B + (size_t)(k0+bK)*N + colBase + bN);
            } else {
                float tmp[4];
                #pragma unroll
                for (int j=0;j<4;j++){
                    int col = colBase + bN + j;
                    tmp[j] = (col < N) ? B[(size_t)(k0+bK)*N + col] : 0.f;
                }
                bReg = make_float4(tmp[0],tmp[1],tmp[2],tmp[3]);
            }
        }
        // compute current buffer
        {
            uint32_t af[4][4], bf[4][2];
            int mBase = warpM*64 + gid;
            #pragma unroll
            for (int mt=0;mt<4;mt++){
                int m0 = mBase + mt*16;
                af[mt][0] = As[buf][tg*SA + m0];
                af[mt][1] = As[buf][tg*SA + m0 + 8];
                af[mt][2] = As[buf][(tg+4)*SA + m0];
                af[mt][3] = As[buf][(tg+4)*SA + m0 + 8];
            }
            int nBase = warpN*32 + gid;
            #pragma unroll
            for (int nt=0;nt<4;nt++){
                int n0 = nBase + nt*8;
                bf[nt][0] = Bs[buf][tg*SA + n0];
                bf[nt][1] = Bs[buf][(tg+4)*SA + n0];
            }
            #pragma unroll
            for (int mt=0;mt<4;mt++)
                #pragma unroll
                for (int nt=0;nt<4;nt++)
                    MMA_TF32(acc[mt][nt], af[mt], bf[nt]);
        }
        // store prefetched tile to other buffer
        if (kt+1 < KT){
            int nb = (kt+1) & 1;
            As[nb][(aK+0)*SA + aRow] = f2tf32(aReg.x);
            As[nb][(aK+1)*SA + aRow] = f2tf32(aReg.y);
            As[nb][(aK+2)*SA + aRow] = f2tf32(aReg.z);
            As[nb][(aK+3)*SA + aRow] = f2tf32(aReg.w);
            uint4 bv = make_uint4(f2tf32(bReg.x),f2tf32(bReg.y),f2tf32(bReg.z),f2tf32(bReg.w));
            *(uint4*)&Bs[nb][bK*SA + bN] = bv;
        }
        __syncthreads();
    }

    // epilogue
    #pragma unroll
    for (int mt=0;mt<4;mt++){
        int row0 = blockIdx.y*128 + warpM*64 + mt*16 + gid;
        #pragma unroll
        for (int nt=0;nt<4;nt++){
            int col = colBase + warpN*32 + nt*8 + tg*2;
            if (col < N){
                float2 v0 = make_float2(acc[mt][nt][0], acc[mt][nt][1]);
                float2 v1 = make_float2(acc[mt][nt][2], acc[mt][nt][3]);
                if (Cadd){
                    float2 r0 = *(const float2*)(Cadd + (size_t)row0*N + col);
                    float2 r1 = *(const float2*)(Cadd + (size_t)(row0+8)*N + col);
                    v0.x += r0.x; v0.y += r0.y;
                    v1.x += r1.x; v1.y += r1.y;
                }
                *(float2*)(C + (size_t)row0*N + col) = v0;
                *(float2*)(C + (size_t)(row0+8)*N + col) = v1;
            }
        }
    }
}

// ---------------- K3: causal depthwise conv1d (k=4) + bias + SiLU ----------------
__global__ void conv_kernel(const float* __restrict__ zx, const float* __restrict__ cw,
                            const float* __restrict__ cb, float* __restrict__ out){
    int idx = blockIdx.x*blockDim.x + threadIdx.x;
    if (idx >= NTOK*CONVDIM) return;
    int c = idx % CONVDIM;
    int row = idx / CONVDIM;
    int l = row & (LL-1);
    float acc = cb[c];
    #pragma unroll
    for (int k=0;k<4;k++){
        int ls = l - 3 + k;
        if (ls >= 0) acc += zx[(size_t)(row-3+k)*DPROJ + DIN + c] * cw[c*4+k];
    }
    out[(size_t)row*CONVDIM + c] = siluf(acc);
}

// ---------------- K4: dt = softplus(dt_raw + dt_bias) ----------------
__global__ void dt_kernel(const float* __restrict__ zx, const float* __restrict__ dt_bias,
                          float* __restrict__ dtv){
    int idx = blockIdx.x*blockDim.x + threadIdx.x;
    if (idx >= NTOK*NH) return;
    int h = idx & (NH-1);
    int row = idx / NH;
    float x = zx[(size_t)row*DPROJ + (DIN + CONVDIM) + h] + dt_bias[h];
    dtv[idx] = (x > 20.f) ? x : log1pf(expf(x));
}

// ---------------- K5: per-(b,c,h) inclusive cumsum of dt*A over chunk ----------------
__global__ __launch_bounds__(256) void cumsum_kernel(const float* __restrict__ dtv,
                                                     const float* __restrict__ A_log,
                                                     float* __restrict__ Acum){
    int bid = blockIdx.x;
    int h = bid % NH; int c = (bid/NH) % NCHK; int b = bid/(NH*NCHK);
    int t = threadIdx.x;
    int row = b*LL + c*CHUNKSZ + t;
    float negA = -expf(A_log[h]);
    float v = dtv[(size_t)row*NH + h] * negA;
    __shared__ float sh[256];
    sh[t] = v; __syncthreads();
    for (int off=1; off<256; off<<=1){
        float add = (t >= off) ? sh[t-off] : 0.f;
        __syncthreads();
        sh[t] += add;
        __syncthreads();
    }
    Acum[(size_t)bid*CHUNKSZ + t] = sh[t];
}

// ---------------- K6: G[l,s] = sum_n C[l,n]*B[s,n], per (b,c) ----------------
__global__ __launch_bounds__(256) void gmat_kernel(const float* __restrict__ xbc,
                                                   float* __restrict__ G){
    int bc = blockIdx.z;
    int b = bc / NCHK, c = bc % NCHK;
    int lt = blockIdx.x*16, st = blockIdx.y*16;
    __shared__ float Cs[16][129];
    __shared__ float Bs[16][129];
    int t = threadIdx.y*16 + threadIdx.x;
    int rowbase = b*LL + c*CHUNKSZ;
    #pragma unroll
    for (int i=0;i<8;i++){
        int f = i*256 + t; int r = f >> 7, col = f & 127;
        Cs[r][col] = xbc[(size_t)(rowbase+lt+r)*CONVDIM + 2176 + col];
        Bs[r][col] = xbc[(size_t)(rowbase+st+r)*CONVDIM + 2048 + col];
    }
    __syncthreads();
    float acc = 0.f;
    #pragma unroll 8
    for (int n=0;n<128;n++) acc += Cs[threadIdx.y][n]*Bs[threadIdx.x][n];
    G[((size_t)bc*CHUNKSZ + lt + threadIdx.y)*CHUNKSZ + st + threadIdx.x] = acc;
}

// ---------------- K7: Y_diag per (b,c,h) ----------------
__global__ __launch_bounds__(256) void ydiag_kernel(const float* __restrict__ xbc,
                                                    const float* __restrict__ dtv,
                                                    const float* __restrict__ Acum,
                                                    const float* __restrict__ G,
                                                    float* __restrict__ ydiag){
    int bid = blockIdx.x;
    int h = bid % NH; int c = (bid/NH) % NCHK; int b = bid/(NH*NCHK);
    int t = threadIdx.x;
    int bc = b*NCHK + c;
    int rowbase = b*LL + c*CHUNKSZ;
    const float* Gb = G + (size_t)bc*CHUNKSZ*CHUNKSZ;

    __shared__ float Gs[256*33];
    __shared__ float xs[32*64];
    __shared__ float Acs[32];
    __shared__ float dts[32];

    float a_l = Acum[(size_t)bid*CHUNKSZ + t];
    float acc[64];
    #pragma unroll
    for (int p=0;p<64;p++) acc[p] = 0.f;

    for (int s0=0; s0<CHUNKSZ; s0+=32){
        #pragma unroll 4
        for (int i=0;i<32;i++){
            int f = i*256 + t; int r = f >> 5, col = f & 31;
            Gs[r*33+col] = Gb[(size_t)r*CHUNKSZ + s0 + col];
        }
        #pragma unroll
        for (int i=0;i<8;i++){
            int f = i*256 + t; int s = f >> 6, p = f & 63;
            xs[s*64+p] = xbc[(size_t)(rowbase+s0+s)*CONVDIM + h*HD + p];
        }
        if (t < 32){
            Acs[t] = Acum[(size_t)bid*CHUNKSZ + s0 + t];
            dts[t] = dtv[(size_t)(rowbase+s0+t)*NH + h];
        }
        __syncthreads();
        if (s0 <= t){
            int smax = t - s0 + 1; if (smax > 32) smax = 32;
            for (int s=0;s<smax;s++){
                float coef = Gs[t*33+s] * __expf(a_l - Acs[s]) * dts[s];
                const float* xp = &xs[s*64];
                #pragma unroll
                for (int p=0;p<64;p++) acc[p] += coef * xp[p];
            }
        }
        __syncthreads();
    }
    float* yo = ydiag + (size_t)(rowbase+t)*DIN + h*HD;
    #pragma unroll
    for (int p=0;p<64;p+=4)
        *(float4*)(yo+p) = make_float4(acc[p],acc[p+1],acc[p+2],acc[p+3]);
}

// ---------------- K8: chunk states per (b,c,h) ----------------
__global__ __launch_bounds__(256) void states_kernel(const float* __restrict__ xbc,
                                                     const float* __restrict__ dtv,
                                                     const float* __restrict__ Acum,
                                                     float* __restrict__ states){
    int bid = blockIdx.x;
    int h = bid % NH; int c = (bid/NH) % NCHK; int b = bid/(NH*NCHK);
    int t = threadIdx.x;
    int p = t & 63, ng = t >> 6;
    int rowbase = b*LL + c*CHUNKSZ;

    __shared__ float xs[32*64];
    __shared__ float Bsh[32*128];
    __shared__ float cl[32];

    float Atot = Acum[(size_t)bid*CHUNKSZ + 255];
    float acc[32];
    #pragma unroll
    for (int j=0;j<32;j++) acc[j] = 0.f;

    for (int l0=0; l0<CHUNKSZ; l0+=32){
        #pragma unroll
        for (int i=0;i<8;i++){
            int f = i*256 + t; int s = f >> 6, pp = f & 63;
            xs[s*64+pp] = xbc[(size_t)(rowbase+l0+s)*CONVDIM + h*HD + pp];
        }
        #pragma unroll
        for (int i=0;i<16;i++){
            int f = i*256 + t; int r = f >> 7, n = f & 127;
            Bsh[r*128+n] = xbc[(size_t)(rowbase+l0+r)*CONVDIM + 2048 + n];
        }
        if (t < 32){
            int l = l0 + t;
            cl[t] = dtv[(size_t)(rowbase+l)*NH + h] * __expf(Atot - Acum[(size_t)bid*CHUNKSZ + l]);
        }
        __syncthreads();
        for (int l=0;l<32;l++){
            float v = xs[l*64+p] * cl[l];
            const float* bp = &Bsh[l*128 + ng*32];
            #pragma unroll
            for (int j=0;j<32;j++) acc[j] += v * bp[j];
        }
        __syncthreads();
    }
    float* so = states + ((size_t)bid*HD + p)*DS + ng*32;
    #pragma unroll
    for (int j=0;j<32;j+=4)
        *(float4*)(so+j) = make_float4(acc[j],acc[j+1],acc[j+2],acc[j+3]);
}

// ---------------- K9: inter-chunk scan ----------------
__global__ void scan_kernel(const float* __restrict__ states, const float* __restrict__ Acum,
                            float* __restrict__ prevS){
    int idx = blockIdx.x*blockDim.x + threadIdx.x;
    if (idx >= BB*NH*HD*DS) return;
    int n = idx & 127;
    int p = (idx >> 7) & 63;
    int h = (idx >> 13) & 31;
    int b = idx >> 18;
    float S = 0.f;
    for (int c=0;c<NCHK;c++){
        int bid = (b*NCHK + c)*NH + h;
        size_t off = ((size_t)bid*HD + p)*DS + n;
        prevS[off] = S;
        float T = Acum[(size_t)bid*CHUNKSZ + 255];
        S = expf(T)*S + states[off];
    }
}

// ---------------- K10: Y_off + combine (in place into ydiag) ----------------
__global__ __launch_bounds__(256) void yoff_kernel(const float* __restrict__ xbc,
                                                   const float* __restrict__ Acum,
                                                   const float* __restrict__ prevS,
                                                   const float* __restrict__ Dskip,
                                                   float* __restrict__ y){
    int bid = blockIdx.x;
    int h = bid % NH; int c = (bid/NH) % NCHK; int b = bid/(NH*NCHK);
    int t = threadIdx.x;
    int rowbase = b*LL + c*CHUNKSZ;

    __shared__ float Ss[64*64];
    __shared__ float Cs[256*17];

    float acc[64];
    #pragma unroll
    for (int p=0;p<64;p++) acc[p] = 0.f;
    const float* Sb = prevS + (size_t)bid*HD*DS;

    for (int half=0; half<2; half++){
        int n0h = half*64;
        __syncthreads();
        #pragma unroll
        for (int i=0;i<16;i++){
            int f = i*256 + t; int pp = f >> 6, j = f & 63;
            Ss[pp*64+j] = Sb[(size_t)pp*DS + n0h + j];
        }
        for (int sub=0; sub<4; sub++){
            int n0 = n0h + sub*16;
            __syncthreads();
            #pragma unroll
            for (int i=0;i<16;i++){
                int f = i*256 + t; int r = f >> 4, cc = f & 15;
                Cs[r*17+cc] = xbc[(size_t)(rowbase+r)*CONVDIM + 2176 + n0 + cc];
            }
            __syncthreads();
            for (int j=0;j<16;j++){
                float cv = Cs[t*17+j];
                int lc = sub*16 + j;
                #pragma unroll
                for (int p=0;p<64;p++) acc[p] += cv * Ss[p*64+lc];
            }
        }
    }
    float e = __expf(Acum[(size_t)bid*CHUNKSZ + t]);
    float dsk = Dskip[h];
    const float* xrow = xbc + (size_t)(rowbase+t)*CONVDIM + h*HD;
    float* yo = y + (size_t)(rowbase+t)*DIN + h*HD;
    #pragma unroll
    for (int p=0;p<64;p+=4){
        float4 xd = *(const float4*)(xrow+p);
        float4 yd = *(const float4*)(yo+p);
        float4 o;
        o.x = yd.x + e*acc[p+0] + xd.x*dsk;
        o.y = yd.y + e*acc[p+1] + xd.y*dsk;
        o.z = yd.z + e*acc[p+2] + xd.z*dsk;
        o.w = yd.w + e*acc[p+3] + xd.w*dsk;
        *(float4*)(yo+p) = o;
    }
}

// ---------------- K11: gated RMSNorm over D_INNER=2048 ----------------
__global__ __launch_bounds__(256) void gatenorm_kernel(const float* __restrict__ y,
                                                       const float* __restrict__ zx,
                                                       const float* __restrict__ gw,
                                                       float* __restrict__ out){
    int row = blockIdx.x, t = threadIdx.x;
    const float* yr = y + (size_t)row*DIN;
    const float* zr = zx + (size_t)row*DPROJ;
    float vals[8]; float ss = 0.f;
    #pragma unroll
    for (int i=0;i<2;i++){
        int cbase = (i*256 + t)*4;
        float4 yv = *(const float4*)(yr + cbase);
        float4 zv = *(const float4*)(zr + cbase);
        float a;
        a = yv.x * siluf(zv.x); vals[i*4+0] = a; ss += a*a;
        a = yv.y * siluf(zv.y); vals[i*4+1] = a; ss += a*a;
        a = yv.z * siluf(zv.z); vals[i*4+2] = a; ss += a*a;
        a = yv.w * siluf(zv.w); vals[i*4+3] = a; ss += a*a;
    }
    __shared__ float red[8];
    for (int o=16;o>0;o>>=1) ss += __shfl_down_sync(0xffffffffu, ss, o);
    if ((t&31)==0) red[t>>5] = ss;
    __syncthreads();
    if (t < 32){
        float s2 = (t<8)? red[t] : 0.f;
        for (int o=4;o>0;o>>=1) s2 += __shfl_down_sync(0xffffffffu, s2, o);
        if (t==0) red[0] = s2;
    }
    __syncthreads();
    float scale = rsqrtf(red[0]/(float)DIN + EPSV);
    #pragma unroll
    for (int i=0;i<2;i++){
        int cbase = (i*256 + t)*4;
        float4 wv = *(const float4*)(gw + cbase);
        float4 o4 = make_float4(vals[i*4+0]*scale*wv.x, vals[i*4+1]*scale*wv.y,
                                vals[i*4+2]*scale*wv.z, vals[i*4+3]*scale*wv.w);
        *(float4*)(out + (size_t)row*DIN + cbase) = o4;
    }
}

// ---------------- launch ----------------
extern "C" void kernel_launch(void* const* d_in, const int* in_sizes, int n_in,
                              void* d_out, int out_size){
    const float* hidden  = (const float*)d_in[0];
    const float* norm_w  = (const float*)d_in[1];
    const float* in_proj = (const float*)d_in[2];
    const float* conv_w  = (const float*)d_in[3];
    const float* conv_b  = (const float*)d_in[4];
    const float* dt_bias = (const float*)d_in[5];
    const float* A_log   = (const float*)d_in[6];
    const float* Dsk     = (const float*)d_in[7];
    const float* gnw     = (const float*)d_in[8];
    const float* out_w   = (const float*)d_in[9];
    float* out = (float*)d_out;

    float *p_xnorm, *p_zx, *p_xbc, *p_dtv, *p_acum, *p_g, *p_states, *p_prevS, *p_ydiag, *p_yg;
    cudaGetSymbolAddress((void**)&p_xnorm, g_xnorm);
    cudaGetSymbolAddress((void**)&p_zx,    g_zxbcdt);
    cudaGetSymbolAddress((void**)&p_xbc,   g_xBCc);
    cudaGetSymbolAddress((void**)&p_dtv,   g_dtv);
    cudaGetSymbolAddress((void**)&p_acum,  g_Acum);
    cudaGetSymbolAddress((void**)&p_g,     g_G);
    cudaGetSymbolAddress((void**)&p_states,g_states);
    cudaGetSymbolAddress((void**)&p_prevS, g_prevS);
    cudaGetSymbolAddress((void**)&p_ydiag, g_ydiag);
    cudaGetSymbolAddress((void**)&p_yg,    g_yg);

    // 1. RMSNorm
    rmsnorm_kernel<<<NTOK, 256>>>(hidden, norm_w, p_xnorm);
    // 2. in_proj GEMM (TF32 tensor cores): [8192,1024] @ [1024,4384]
    tf32gemm_kernel<<<dim3((DPROJ+127)/128, NTOK/128), 256>>>(NTOK, DPROJ, DM, p_xnorm, in_proj, nullptr, p_zx);
    // 3. conv1d + bias + silu
    conv_kernel<<<(NTOK*CONVDIM + 255)/256, 256>>>(p_zx, conv_w, conv_b, p_xbc);
    // 4. dt softplus
    dt_kernel<<<(NTOK*NH + 255)/256, 256>>>(p_zx, dt_bias, p_dtv);
    // 5. per-chunk cumsum of dt*A
    cumsum_kernel<<<BB*NCHK*NH, 256>>>(p_dtv, A_log, p_acum);
    // 6. G = C @ B^T per (b,c)
    gmat_kernel<<<dim3(16,16,BB*NCHK), dim3(16,16)>>>(p_xbc, p_g);
    // 7. Y_diag
    ydiag_kernel<<<BB*NCHK*NH, 256>>>(p_xbc, p_dtv, p_acum, p_g, p_ydiag);
    // 8. chunk states
    states_kernel<<<BB*NCHK*NH, 256>>>(p_xbc, p_dtv, p_acum, p_states);
    // 9. inter-chunk scan
    scan_kernel<<<(BB*NH*HD*DS + 255)/256, 256>>>(p_states, p_acum, p_prevS);
    // 10. Y_off + combine + D skip (in place into ydiag)
    yoff_kernel<<<BB*NCHK*NH, 256>>>(p_xbc, p_acum, p_prevS, Dsk, p_ydiag);
    // 11. gated RMSNorm
    gatenorm_kernel<<<NTOK, 256>>>(p_ydiag, p_zx, gnw, p_yg);
    // 12. out_proj GEMM (TF32) + residual: [8192,2048] @ [2048,1024] + hidden
    tf32gemm_kernel<<<dim3(DM/128, NTOK/128), 256>>>(NTOK, DM, DIN, p_yg, out_w, hidden, out);
}

// round 5
// speedup vs baseline: 2.0785x; 1.0936x over previous
#include <cuda_runtime.h>
#include <math.h>
#include <stdint.h>

// ---------------- problem constants ----------------
#define BB 2
#define LL 4096
#define DM 1024
#define DIN 2048
#define NH 32
#define HD 64
#define DS 128
#define CHUNKSZ 256
#define NCHK 16
#define CONVDIM 2304        // DIN + 2*DS
#define DPROJ 4384          // 2*DIN + 2*DS + NH
#define NTOK (BB*LL)        // 8192
#define EPSV 1e-5f

// ---------------- scratch (device globals; no allocs allowed) ----------------
__device__ float g_xnorm[(size_t)NTOK*DM];
__device__ float g_zxbcdt[(size_t)NTOK*DPROJ];
__device__ float g_xBCc[(size_t)NTOK*CONVDIM];
__device__ float g_dtv[(size_t)NTOK*NH];
__device__ float g_Acum[(size_t)BB*NCHK*NH*CHUNKSZ];
__device__ float g_G[(size_t)BB*NCHK*CHUNKSZ*CHUNKSZ];
__device__ float g_states[(size_t)BB*NCHK*NH*HD*DS];
__device__ float g_prevS[(size_t)BB*NCHK*NH*HD*DS];
__device__ float g_ydiag[(size_t)NTOK*DIN];             // also final y (in place)
__device__ float g_yg[(size_t)NTOK*DIN];

__device__ __forceinline__ float siluf(float x){ return x / (1.f + __expf(-x)); }

__device__ __forceinline__ uint32_t f2tf32(float x){
    uint32_t r;
    asm("cvt.rna.tf32.f32 %0, %1;" : "=r"(r) : "f"(x));
    return r;
}

__device__ __forceinline__ uint32_t smem_u32(const void* p){
    uint32_t a;
    asm("{ .reg .u64 t; cvta.to.shared.u64 t, %1; cvt.u32.u64 %0, t; }" : "=r"(a) : "l"(p));
    return a;
}

__device__ __forceinline__ void cpa16(uint32_t dst, const void* src, bool pred){
    int sz = pred ? 16 : 0;
    asm volatile("cp.async.cg.shared.global [%0], [%1], 16, %2;" :: "r"(dst), "l"(src), "r"(sz));
}

#define CP_COMMIT() asm volatile("cp.async.commit_group;")
#define CP_WAIT1()  asm volatile("cp.async.wait_group 1;")

#define MMA_TF32(c, a, b) \
    asm volatile("mma.sync.aligned.m16n8k8.row.col.f32.tf32.tf32.f32 " \
        "{%0,%1,%2,%3}, {%4,%5,%6,%7}, {%8,%9}, {%0,%1,%2,%3};" \
        : "+f"((c)[0]),"+f"((c)[1]),"+f"((c)[2]),"+f"((c)[3]) \
        : "r"((a)[0]),"r"((a)[1]),"r"((a)[2]),"r"((a)[3]), "r"((b)[0]),"r"((b)[1]))

// ---------------- K1: RMSNorm over D_MODEL=1024 ----------------
__global__ __launch_bounds__(256) void rmsnorm_kernel(const float* __restrict__ x,
                                                      const float* __restrict__ w,
                                                      float* __restrict__ out){
    int row = blockIdx.x;
    int t = threadIdx.x;
    float4 v = ((const float4*)(x + (size_t)row*DM))[t];
    float ss = v.x*v.x + v.y*v.y + v.z*v.z + v.w*v.w;
    __shared__ float red[8];
    for (int o=16;o>0;o>>=1) ss += __shfl_down_sync(0xffffffffu, ss, o);
    if ((t&31)==0) red[t>>5] = ss;
    __syncthreads();
    if (t < 32){
        float s2 = (t<8)? red[t] : 0.f;
        for (int o=4;o>0;o>>=1) s2 += __shfl_down_sync(0xffffffffu, s2, o);
        if (t==0) red[0] = s2;
    }
    __syncthreads();
    float scale = rsqrtf(red[0]/(float)DM + EPSV);
    float4 wv = ((const float4*)w)[t];
    float4 o4 = make_float4(v.x*scale*wv.x, v.y*scale*wv.y, v.z*scale*wv.z, v.w*scale*wv.w);
    ((float4*)(out + (size_t)row*DM))[t] = o4;
}

// ---------------- TF32 GEMM with 3-stage cp.async pipeline ----------------
// C = A(MxK) @ B(KxN) [+ Cadd]; BM=BN=128, BK=16, 8 warps (2x4), 64x32 warp tile.
#define ASTRIDE 20
#define BSTRIDE 136
#define ASTG (128*ASTRIDE)     // floats per A stage
#define BSTG (16*BSTRIDE)      // floats per B stage
#define NSTAGE 3
#define GEMM_SMEM ((NSTAGE*ASTG + NSTAGE*BSTG)*4)

__global__ __launch_bounds__(256) void tf32gemm_kernel(int M, int N, int K,
                                                       const float* __restrict__ A,
                                                       const float* __restrict__ B,
                                                       const float* __restrict__ Cadd,
                                                       float* __restrict__ C){
    extern __shared__ float smem[];
    float* As = smem;
    float* Bs = smem + NSTAGE*ASTG;
    uint32_t aSm = smem_u32(As);
    uint32_t bSm = smem_u32(Bs);

    int tid = threadIdx.x, lane = tid & 31, warp = tid >> 5;
    int warpM = warp & 1, warpN = warp >> 1;
    int gid = lane >> 2, tg = lane & 3;
    int rowBlk = blockIdx.y*128, colBase = blockIdx.x*128;

    // copy mappings
    int aRow = tid >> 1, aKc = (tid & 1)*8;          // A: 128 rows x 16 k
    int bK = tid >> 4, bNc = (tid & 15)*8;           // B: 16 k x 128 n

    const float* Ag = A + (size_t)(rowBlk + aRow)*K + aKc;
    const float* Bg = B + (size_t)bK*N + colBase + bNc;
    bool p0 = (colBase + bNc) < N;
    bool p1 = (colBase + bNc + 4) < N;

    float acc[4][4][4] = {};

    int KT = K >> 4;

    // prologue: issue stages 0,1
    #pragma unroll
    for (int s=0; s<2; s++){
        uint32_t ad = aSm + (uint32_t)(s*ASTG + aRow*ASTRIDE + aKc)*4;
        const float* ap = Ag + s*16;
        cpa16(ad, ap, true);
        cpa16(ad+16, ap+4, true);
        uint32_t bd = bSm + (uint32_t)(s*BSTG + bK*BSTRIDE + bNc)*4;
        const float* bp = Bg + (size_t)s*16*N;
        cpa16(bd, p0 ? bp : B, p0);
        cpa16(bd+16, p1 ? bp+4 : B, p1);
        CP_COMMIT();
    }

    for (int kt=0; kt<KT; kt++){
        int s = kt % NSTAGE;
        CP_WAIT1();
        __syncthreads();
        // issue stage kt+2
        if (kt+2 < KT){
            int s2 = (kt+2) % NSTAGE;
            uint32_t ad = aSm + (uint32_t)(s2*ASTG + aRow*ASTRIDE + aKc)*4;
            const float* ap = Ag + (kt+2)*16;
            cpa16(ad, ap, true);
            cpa16(ad+16, ap+4, true);
            uint32_t bd = bSm + (uint32_t)(s2*BSTG + bK*BSTRIDE + bNc)*4;
            const float* bp = Bg + (size_t)(kt+2)*16*N;
            cpa16(bd, p0 ? bp : B, p0);
            cpa16(bd+16, p1 ? bp+4 : B, p1);
        }
        CP_COMMIT();

        const float* ab = As + s*ASTG;
        const float* bb = Bs + s*BSTG;
        #pragma unroll
        for (int kk=0; kk<2; kk++){
            int kc = kk*8;
            uint32_t af[4][4], bf[4][2];
            #pragma unroll
            for (int mt=0;mt<4;mt++){
                int m0 = warpM*64 + mt*16 + gid;
                af[mt][0] = f2tf32(ab[(m0  )*ASTRIDE + kc + tg]);
                af[mt][1] = f2tf32(ab[(m0+8)*ASTRIDE + kc + tg]);
                af[mt][2] = f2tf32(ab[(m0  )*ASTRIDE + kc + tg + 4]);
                af[mt][3] = f2tf32(ab[(m0+8)*ASTRIDE + kc + tg + 4]);
            }
            #pragma unroll
            for (int nt=0;nt<4;nt++){
                int n0 = warpN*32 + nt*8 + gid;
                bf[nt][0] = f2tf32(bb[(kc+tg  )*BSTRIDE + n0]);
                bf[nt][1] = f2tf32(bb[(kc+tg+4)*BSTRIDE + n0]);
            }
            #pragma unroll
            for (int mt=0;mt<4;mt++)
                #pragma unroll
                for (int nt=0;nt<4;nt++)
                    MMA_TF32(acc[mt][nt], af[mt], bf[nt]);
        }
    }

    // epilogue
    #pragma unroll
    for (int mt=0;mt<4;mt++){
        int row0 = rowBlk + warpM*64 + mt*16 + gid;
        #pragma unroll
        for (int nt=0;nt<4;nt++){
            int col = colBase + warpN*32 + nt*8 + tg*2;
            if (col < N){
                float2 v0 = make_float2(acc[mt][nt][0], acc[mt][nt][1]);
                float2 v1 = make_float2(acc[mt][nt][2], acc[mt][nt][3]);
                if (Cadd){
                    float2 r0 = *(const float2*)(Cadd + (size_t)row0*N + col);
                    float2 r1 = *(const float2*)(Cadd + (size_t)(row0+8)*N + col);
                    v0.x += r0.x; v0.y += r0.y;
                    v1.x += r1.x; v1.y += r1.y;
                }
                *(float2*)(C + (size_t)row0*N + col) = v0;
                *(float2*)(C + (size_t)(row0+8)*N + col) = v1;
            }
        }
    }
}

// ---------------- K3: causal depthwise conv1d (k=4) + bias + SiLU ----------------
__global__ void conv_kernel(const float* __restrict__ zx, const float* __restrict__ cw,
                            const float* __restrict__ cb, float* __restrict__ out){
    int idx = blockIdx.x*blockDim.x + threadIdx.x;
    if (idx >= NTOK*CONVDIM) return;
    int c = idx % CONVDIM;
    int row = idx / CONVDIM;
    int l = row & (LL-1);
    float acc = cb[c];
    #pragma unroll
    for (int k=0;k<4;k++){
        int ls = l - 3 + k;
        if (ls >= 0) acc += zx[(size_t)(row-3+k)*DPROJ + DIN + c] * cw[c*4+k];
    }
    out[(size_t)row*CONVDIM + c] = siluf(acc);
}

// ---------------- K4: dt = softplus(dt_raw + dt_bias) ----------------
__global__ void dt_kernel(const float* __restrict__ zx, const float* __restrict__ dt_bias,
                          float* __restrict__ dtv){
    int idx = blockIdx.x*blockDim.x + threadIdx.x;
    if (idx >= NTOK*NH) return;
    int h = idx & (NH-1);
    int row = idx / NH;
    float x = zx[(size_t)row*DPROJ + (DIN + CONVDIM) + h] + dt_bias[h];
    dtv[idx] = (x > 20.f) ? x : log1pf(expf(x));
}

// ---------------- K5: per-(b,c,h) inclusive cumsum of dt*A over chunk ----------------
__global__ __launch_bounds__(256) void cumsum_kernel(const float* __restrict__ dtv,
                                                     const float* __restrict__ A_log,
                                                     float* __restrict__ Acum){
    int bid = blockIdx.x;
    int h = bid % NH; int c = (bid/NH) % NCHK; int b = bid/(NH*NCHK);
    int t = threadIdx.x;
    int row = b*LL + c*CHUNKSZ + t;
    float negA = -expf(A_log[h]);
    float v = dtv[(size_t)row*NH + h] * negA;
    __shared__ float sh[256];
    sh[t] = v; __syncthreads();
    for (int off=1; off<256; off<<=1){
        float add = (t >= off) ? sh[t-off] : 0.f;
        __syncthreads();
        sh[t] += add;
        __syncthreads();
    }
    Acum[(size_t)bid*CHUNKSZ + t] = sh[t];
}

// ---------------- K6: G[l,s] = sum_n C[l,n]*B[s,n], per (b,c) ----------------
__global__ __launch_bounds__(256) void gmat_kernel(const float* __restrict__ xbc,
                                                   float* __restrict__ G){
    int bc = blockIdx.z;
    int b = bc / NCHK, c = bc % NCHK;
    int lt = blockIdx.x*16, st = blockIdx.y*16;
    __shared__ float Cs[16][129];
    __shared__ float Bs[16][129];
    int t = threadIdx.y*16 + threadIdx.x;
    int rowbase = b*LL + c*CHUNKSZ;
    #pragma unroll
    for (int i=0;i<8;i++){
        int f = i*256 + t; int r = f >> 7, col = f & 127;
        Cs[r][col] = xbc[(size_t)(rowbase+lt+r)*CONVDIM + 2176 + col];
        Bs[r][col] = xbc[(size_t)(rowbase+st+r)*CONVDIM + 2048 + col];
    }
    __syncthreads();
    float acc = 0.f;
    #pragma unroll 8
    for (int n=0;n<128;n++) acc += Cs[threadIdx.y][n]*Bs[threadIdx.x][n];
    G[((size_t)bc*CHUNKSZ + lt + threadIdx.y)*CHUNKSZ + st + threadIdx.x] = acc;
}

// ---------------- K7: Y_diag per (b,c,h) ----------------
__global__ __launch_bounds__(256) void ydiag_kernel(const float* __restrict__ xbc,
                                                    const float* __restrict__ dtv,
                                                    const float* __restrict__ Acum,
                                                    const float* __restrict__ G,
                                                    float* __restrict__ ydiag){
    int bid = blockIdx.x;
    int h = bid % NH; int c = (bid/NH) % NCHK; int b = bid/(NH*NCHK);
    int t = threadIdx.x;
    int bc = b*NCHK + c;
    int rowbase = b*LL + c*CHUNKSZ;
    const float* Gb = G + (size_t)bc*CHUNKSZ*CHUNKSZ;

    __shared__ float Gs[256*33];
    __shared__ float xs[32*64];
    __shared__ float Acs[32];
    __shared__ float dts[32];

    float a_l = Acum[(size_t)bid*CHUNKSZ + t];
    float acc[64];
    #pragma unroll
    for (int p=0;p<64;p++) acc[p] = 0.f;

    for (int s0=0; s0<CHUNKSZ; s0+=32){
        #pragma unroll 4
        for (int i=0;i<32;i++){
            int f = i*256 + t; int r = f >> 5, col = f & 31;
            Gs[r*33+col] = Gb[(size_t)r*CHUNKSZ + s0 + col];
        }
        #pragma unroll
        for (int i=0;i<8;i++){
            int f = i*256 + t; int s = f >> 6, p = f & 63;
            xs[s*64+p] = xbc[(size_t)(rowbase+s0+s)*CONVDIM + h*HD + p];
        }
        if (t < 32){
            Acs[t] = Acum[(size_t)bid*CHUNKSZ + s0 + t];
            dts[t] = dtv[(size_t)(rowbase+s0+t)*NH + h];
        }
        __syncthreads();
        if (s0 <= t){
            int smax = t - s0 + 1; if (smax > 32) smax = 32;
            for (int s=0;s<smax;s++){
                float coef = Gs[t*33+s] * __expf(a_l - Acs[s]) * dts[s];
                const float4* xp4 = (const float4*)&xs[s*64];
                #pragma unroll
                for (int p4=0;p4<16;p4++){
                    float4 xv = xp4[p4];
                    acc[p4*4+0] += coef*xv.x;
                    acc[p4*4+1] += coef*xv.y;
                    acc[p4*4+2] += coef*xv.z;
                    acc[p4*4+3] += coef*xv.w;
                }
            }
        }
        __syncthreads();
    }
    float* yo = ydiag + (size_t)(rowbase+t)*DIN + h*HD;
    #pragma unroll
    for (int p=0;p<64;p+=4)
        *(float4*)(yo+p) = make_float4(acc[p],acc[p+1],acc[p+2],acc[p+3]);
}

// ---------------- K8: chunk states per (b,c,h) ----------------
__global__ __launch_bounds__(256) void states_kernel(const float* __restrict__ xbc,
                                                     const float* __restrict__ dtv,
                                                     const float* __restrict__ Acum,
                                                     float* __restrict__ states){
    int bid = blockIdx.x;
    int h = bid % NH; int c = (bid/NH) % NCHK; int b = bid/(NH*NCHK);
    int t = threadIdx.x;
    int p = t & 63, ng = t >> 6;
    int rowbase = b*LL + c*CHUNKSZ;

    __shared__ float xs[32*64];
    __shared__ float Bsh[32*128];
    __shared__ float cl[32];

    float Atot = Acum[(size_t)bid*CHUNKSZ + 255];
    float acc[32];
    #pragma unroll
    for (int j=0;j<32;j++) acc[j] = 0.f;

    for (int l0=0; l0<CHUNKSZ; l0+=32){
        #pragma unroll
        for (int i=0;i<8;i++){
            int f = i*256 + t; int s = f >> 6, pp = f & 63;
            xs[s*64+pp] = xbc[(size_t)(rowbase+l0+s)*CONVDIM + h*HD + pp];
        }
        #pragma unroll
        for (int i=0;i<16;i++){
            int f = i*256 + t; int r = f >> 7, n = f & 127;
            Bsh[r*128+n] = xbc[(size_t)(rowbase+l0+r)*CONVDIM + 2048 + n];
        }
        if (t < 32){
            int l = l0 + t;
            cl[t] = dtv[(size_t)(rowbase+l)*NH + h] * __expf(Atot - Acum[(size_t)bid*CHUNKSZ + l]);
        }
        __syncthreads();
        for (int l=0;l<32;l++){
            float v = xs[l*64+p] * cl[l];
            const float4* bp4 = (const float4*)&Bsh[l*128 + ng*32];
            #pragma unroll
            for (int j4=0;j4<8;j4++){
                float4 bv = bp4[j4];
                acc[j4*4+0] += v*bv.x;
                acc[j4*4+1] += v*bv.y;
                acc[j4*4+2] += v*bv.z;
                acc[j4*4+3] += v*bv.w;
            }
        }
        __syncthreads();
    }
    float* so = states + ((size_t)bid*HD + p)*DS + ng*32;
    #pragma unroll
    for (int j=0;j<32;j+=4)
        *(float4*)(so+j) = make_float4(acc[j],acc[j+1],acc[j+2],acc[j+3]);
}

// ---------------- K9: inter-chunk scan ----------------
__global__ void scan_kernel(const float* __restrict__ states, const float* __restrict__ Acum,
                            float* __restrict__ prevS){
    int idx = blockIdx.x*blockDim.x + threadIdx.x;
    if (idx >= BB*NH*HD*DS) return;
    int n = idx & 127;
    int p = (idx >> 7) & 63;
    int h = (idx >> 13) & 31;
    int b = idx >> 18;
    float S = 0.f;
    for (int c=0;c<NCHK;c++){
        int bid = (b*NCHK + c)*NH + h;
        size_t off = ((size_t)bid*HD + p)*DS + n;
        prevS[off] = S;
        float T = Acum[(size_t)bid*CHUNKSZ + 255];
        S = expf(T)*S + states[off];
    }
}

// ---------------- K10: Y_off + combine (in place into ydiag) ----------------
__global__ __launch_bounds__(256) void yoff_kernel(const float* __restrict__ xbc,
                                                   const float* __restrict__ Acum,
                                                   const float* __restrict__ prevS,
                                                   const float* __restrict__ Dskip,
                                                   float* __restrict__ y){
    int bid = blockIdx.x;
    int h = bid % NH; int c = (bid/NH) % NCHK; int b = bid/(NH*NCHK);
    int t = threadIdx.x;
    int rowbase = b*LL + c*CHUNKSZ;

    __shared__ float Sst[64*68];      // transposed: [n][p], stride 68
    __shared__ float Cs[256*17];

    float acc[64];
    #pragma unroll
    for (int p=0;p<64;p++) acc[p] = 0.f;
    const float* Sb = prevS + (size_t)bid*HD*DS;

    for (int half=0; half<2; half++){
        int n0h = half*64;
        __syncthreads();   // prior compute done before overwriting Sst
        #pragma unroll
        for (int i=0;i<16;i++){
            int f = i*256 + t; int pp = f >> 6, j = f & 63;
            Sst[j*68+pp] = Sb[(size_t)pp*DS + n0h + j];
        }
        for (int sub=0; sub<4; sub++){
            int n0 = n0h + sub*16;
            __syncthreads();
            #pragma unroll
            for (int i=0;i<16;i++){
                int f = i*256 + t; int r = f >> 4, cc = f & 15;
                Cs[r*17+cc] = xbc[(size_t)(rowbase+r)*CONVDIM + 2176 + n0 + cc];
            }
            __syncthreads();
            for (int j=0;j<16;j++){
                float cv = Cs[t*17+j];
                const float4* sp = (const float4*)&Sst[(sub*16+j)*68];
                #pragma unroll
                for (int p4=0;p4<16;p4++){
                    float4 sv = sp[p4];
                    acc[p4*4+0] += cv*sv.x;
                    acc[p4*4+1] += cv*sv.y;
                    acc[p4*4+2] += cv*sv.z;
                    acc[p4*4+3] += cv*sv.w;
                }
            }
        }
    }
    float e = __expf(Acum[(size_t)bid*CHUNKSZ + t]);
    float dsk = Dskip[h];
    const float* xrow = xbc + (size_t)(rowbase+t)*CONVDIM + h*HD;
    float* yo = y + (size_t)(rowbase+t)*DIN + h*HD;
    #pragma unroll
    for (int p=0;p<64;p+=4){
        float4 xd = *(const float4*)(xrow+p);
        float4 yd = *(const float4*)(yo+p);
        float4 o;
        o.x = yd.x + e*acc[p+0] + xd.x*dsk;
        o.y = yd.y + e*acc[p+1] + xd.y*dsk;
        o.z = yd.z + e*acc[p+2] + xd.z*dsk;
        o.w = yd.w + e*acc[p+3] + xd.w*dsk;
        *(float4*)(yo+p) = o;
    }
}

// ---------------- K11: gated RMSNorm over D_INNER=2048 ----------------
__global__ __launch_bounds__(256) void gatenorm_kernel(const float* __restrict__ y,
                                                       const float* __restrict__ zx,
                                                       const float* __restrict__ gw,
                                                       float* __restrict__ out){
    int row = blockIdx.x, t = threadIdx.x;
    const float* yr = y + (size_t)row*DIN;
    const float* zr = zx + (size_t)row*DPROJ;
    float vals[8]; float ss = 0.f;
    #pragma unroll
    for (int i=0;i<2;i++){
        int cbase = (i*256 + t)*4;
        float4 yv = *(const float4*)(yr + cbase);
        float4 zv = *(const float4*)(zr + cbase);
        float a;
        a = yv.x * siluf(zv.x); vals[i*4+0] = a; ss += a*a;
        a = yv.y * siluf(zv.y); vals[i*4+1] = a; ss += a*a;
        a = yv.z * siluf(zv.z); vals[i*4+2] = a; ss += a*a;
        a = yv.w * siluf(zv.w); vals[i*4+3] = a; ss += a*a;
    }
    __shared__ float red[8];
    for (int o=16;o>0;o>>=1) ss += __shfl_down_sync(0xffffffffu, ss, o);
    if ((t&31)==0) red[t>>5] = ss;
    __syncthreads();
    if (t < 32){
        float s2 = (t<8)? red[t] : 0.f;
        for (int o=4;o>0;o>>=1) s2 += __shfl_down_sync(0xffffffffu, s2, o);
        if (t==0) red[0] = s2;
    }
    __syncthreads();
    float scale = rsqrtf(red[0]/(float)DIN + EPSV);
    #pragma unroll
    for (int i=0;i<2;i++){
        int cbase = (i*256 + t)*4;
        float4 wv = *(const float4*)(gw + cbase);
        float4 o4 = make_float4(vals[i*4+0]*scale*wv.x, vals[i*4+1]*scale*wv.y,
                                vals[i*4+2]*scale*wv.z, vals[i*4+3]*scale*wv.w);
        *(float4*)(out + (size_t)row*DIN + cbase) = o4;
    }
}

// ---------------- launch ----------------
extern "C" void kernel_launch(void* const* d_in, const int* in_sizes, int n_in,
                              void* d_out, int out_size){
    const float* hidden  = (const float*)d_in[0];
    const float* norm_w  = (const float*)d_in[1];
    const float* in_proj = (const float*)d_in[2];
    const float* conv_w  = (const float*)d_in[3];
    const float* conv_b  = (const float*)d_in[4];
    const float* dt_bias = (const float*)d_in[5];
    const float* A_log   = (const float*)d_in[6];
    const float* Dsk     = (const float*)d_in[7];
    const float* gnw     = (const float*)d_in[8];
    const float* out_w   = (const float*)d_in[9];
    float* out = (float*)d_out;

    float *p_xnorm, *p_zx, *p_xbc, *p_dtv, *p_acum, *p_g, *p_states, *p_prevS, *p_ydiag, *p_yg;
    cudaGetSymbolAddress((void**)&p_xnorm, g_xnorm);
    cudaGetSymbolAddress((void**)&p_zx,    g_zxbcdt);
    cudaGetSymbolAddress((void**)&p_xbc,   g_xBCc);
    cudaGetSymbolAddress((void**)&p_dtv,   g_dtv);
    cudaGetSymbolAddress((void**)&p_acum,  g_Acum);
    cudaGetSymbolAddress((void**)&p_g,     g_G);
    cudaGetSymbolAddress((void**)&p_states,g_states);
    cudaGetSymbolAddress((void**)&p_prevS, g_prevS);
    cudaGetSymbolAddress((void**)&p_ydiag, g_ydiag);
    cudaGetSymbolAddress((void**)&p_yg,    g_yg);

    cudaFuncSetAttribute(tf32gemm_kernel, cudaFuncAttributeMaxDynamicSharedMemorySize, GEMM_SMEM);

    // 1. RMSNorm
    rmsnorm_kernel<<<NTOK, 256>>>(hidden, norm_w, p_xnorm);
    // 2. in_proj GEMM (TF32 tensor cores, cp.async): [8192,1024] @ [1024,4384]
    tf32gemm_kernel<<<dim3((DPROJ+127)/128, NTOK/128), 256, GEMM_SMEM>>>(NTOK, DPROJ, DM, p_xnorm, in_proj, nullptr, p_zx);
    // 3. conv1d + bias + silu
    conv_kernel<<<(NTOK*CONVDIM + 255)/256, 256>>>(p_zx, conv_w, conv_b, p_xbc);
    // 4. dt softplus
    dt_kernel<<<(NTOK*NH + 255)/256, 256>>>(p_zx, dt_bias, p_dtv);
    // 5. per-chunk cumsum of dt*A
    cumsum_kernel<<<BB*NCHK*NH, 256>>>(p_dtv, A_log, p_acum);
    // 6. G = C @ B^T per (b,c)
    gmat_kernel<<<dim3(16,16,BB*NCHK), dim3(16,16)>>>(p_xbc, p_g);
    // 7. Y_diag
    ydiag_kernel<<<BB*NCHK*NH, 256>>>(p_xbc, p_dtv, p_acum, p_g, p_ydiag);
    // 8. chunk states
    states_kernel<<<BB*NCHK*NH, 256>>>(p_xbc, p_dtv, p_acum, p_states);
    // 9. inter-chunk scan
    scan_kernel<<<(BB*NH*HD*DS + 255)/256, 256>>>(p_states, p_acum, p_prevS);
    // 10. Y_off + combine + D skip (in place into ydiag)
    yoff_kernel<<<BB*NCHK*NH, 256>>>(p_xbc, p_acum, p_prevS, Dsk, p_ydiag);
    // 11. gated RMSNorm
    gatenorm_kernel<<<NTOK, 256>>>(p_ydiag, p_zx, gnw, p_yg);
    // 12. out_proj GEMM (TF32) + residual: [8192,2048] @ [2048,1024] + hidden
    tf32gemm_kernel<<<dim3(DM/128, NTOK/128), 256, GEMM_SMEM>>>(NTOK, DM, DIN, p_yg, out_w, hidden, out);
}